// round 7
// baseline (speedup 1.0000x reference)
#include <cuda_runtime.h>
#include <math.h>

#define BATCH 512
#define LEN   50
#define EMB   512
#define C1    20
#define C2    40
#define EPSV  1e-5f

// ---------------- device scratch ----------------
__device__ float g_A   [2*BATCH*C2*23];   // [side][b][o][x]
__device__ float g_s1  [C2*2*BATCH];      // [o][side][b]
__device__ float g_s2  [C2*2*BATCH];
__device__ float g_bn2 [2*C2];            // scale | shift
__device__ float g_weff[4840];            // Wfc2 @ Wfc1
__device__ float g_bias0;
__device__ float g_Wxy [2*C2*C1*3];       // Wx | Wy

__device__ __forceinline__ void ffma2(unsigned long long& d,
                                      unsigned long long a, unsigned long long b) {
    asm("fma.rn.f32x2 %0, %1, %2, %0;" : "+l"(d) : "l"(a), "l"(b));
}

// dynamic smem layout (bytes) — es/ws double buffered
#define OFF_ES   0          // float4 es4[2][32*32] = 32768
#define OFF_WS   32768      // float2 ws2[2][32*20] = 10240
#define OFF_FS   43008      // float  fs[100*21]    =  8400
#define OFF_M    51408      // float  m[1000]       =  4000
#define OFF_TOK  55408      // int    tok[100]      =   400
#define OFF_BN   55808      // float  bn[80]        =   320
#define SMEM_K1  56128
#define OFF_WXY  0          // wxy[4800] reuses es after GEMM

// ---------------------------------------------------------------------------
// k0: weight-only precomputes
// ---------------------------------------------------------------------------
__global__ void k0(const float* __restrict__ W2, const float* __restrict__ Wfc1,
                   const float* __restrict__ Wfc2, const float* __restrict__ bfc1,
                   const float* __restrict__ bfc2)
{
    const int blk = blockIdx.x, tid = threadIdx.x;
    if (blk < 19) {
        int k = blk*256 + tid;
        if (k < 4840) {
            float w = 0.f;
#pragma unroll
            for (int c = 0; c < 20; c++) w += Wfc2[c]*Wfc1[c*4840 + k];
            g_weff[k] = w;
        }
        if (blk == 0 && tid == 0) {
            float z = bfc2[0];
#pragma unroll
            for (int c = 0; c < 20; c++) z += Wfc2[c]*bfc1[c];
            g_bias0 = z;
        }
    } else {
        int q = (blk - 19)*256 + tid;
        if (q < 4800) {
            int sside = q / 2400, r = q % 2400;
            int o = r / 60, rc = r % 60, c = rc / 3, d = rc % 3;
            const float* w = W2 + (o*20 + c)*9;
            g_Wxy[q] = sside ? (w[d*3+0] + w[d*3+1] + w[d*3+2])
                             : (w[0*3+d] + w[1*3+d] + w[2*3+d]);
        }
    }
}

// ---------------------------------------------------------------------------
// k1: L2 row-burst prefetch + depth-2 LDG pipeline + fused epilogue
// ---------------------------------------------------------------------------
__global__ __launch_bounds__(128, 4)
void k1(const int* __restrict__ src, const int* __restrict__ trg,
        const float* __restrict__ emb_src, const float* __restrict__ emb_trg,
        const float* __restrict__ W1, const float* __restrict__ g1,
        const float* __restrict__ beta1)
{
    extern __shared__ char smraw[];
    float*  esf = (float* )(smraw + OFF_ES);
    float4* es4 = (float4*)(smraw + OFF_ES);
    float2* ws2 = (float2*)(smraw + OFF_WS);
    float*  fs  = (float* )(smraw + OFF_FS);
    float*  m   = (float* )(smraw + OFF_M);
    int*    tok = (int*   )(smraw + OFF_TOK);
    float*  bn  = (float* )(smraw + OFF_BN);
    float*  wxy = (float* )(smraw + OFF_WXY);

    const int tid = threadIdx.x;
    const int b   = blockIdx.x;

    if (tid < 100) {
        int u = tid / 50, l = tid % 50;
        tok[tid] = (u ? trg : src)[b*LEN + l];
    }
    __syncthreads();

    // *** L2 prefetch pass: pull all 100 token rows into L2 as FULL-ROW BURSTS.
    // Consecutive lanes touch consecutive 128B lines of the same row, so DRAM
    // sees 2KB sequential bursts (row-buffer hits) instead of the random 128B
    // slices the j-chunked pipeline below would otherwise generate.
    {
#pragma unroll
        for (int it = 0; it < 13; it++) {
            int q = tid + it*128;           // 1600 lines = 100 rows x 16
            if (q < 1600) {
                int t = q >> 4, ln = q & 15;
                const float* base = (t >= 50) ? emb_trg : emb_src;
                const float* addr = base + (size_t)tok[t]*EMB + ln*32;
                asm volatile("prefetch.global.L2 [%0];" :: "l"(addr));
            }
        }
    }

    // issue LDGs into a register set (no wait here)
    auto prefetch = [&](int h, float4 (&fr)[7], float4 (&wr)[2]) {
#pragma unroll
        for (int it = 0; it < 7; it++) {
            int q = tid + it*128;
            if (q < 800) {
                int t = q >> 3, j4 = q & 7;
                const float* base = (t >= 50) ? emb_trg : emb_src;
                fr[it] = *(const float4*)(base + (size_t)tok[t]*EMB + h*32 + j4*4);
            }
        }
#pragma unroll
        for (int it = 0; it < 2; it++) {
            int q = tid + it*128;
            if (q < 160) {
                int c = q >> 3, j4 = q & 7;
                wr[it] = *(const float4*)(W1 + c*EMB + h*32 + j4*4);
            }
        }
    };
    // regs -> smem buffer `buf` (conflict-free XOR swizzle, verified)
    auto store_stage = [&](float4 (&fr)[7], float4 (&wr)[2], int buf) {
        float* eb = esf + buf*4096;
        float2* wb = ws2 + buf*640;
#pragma unroll
        for (int it = 0; it < 7; it++) {
            int q = tid + it*128;
            if (q < 800) {
                int t = q >> 3, j4 = q & 7;
                int tq = t >> 2, t3 = t & 3;
                int p0 = 512*j4 + 4*(tq ^ j4) + t3;
                eb[p0      ] = fr[it].x;
                eb[p0 + 128] = fr[it].y;
                eb[p0 + 256] = fr[it].z;
                eb[p0 + 384] = fr[it].w;
            }
        }
#pragma unroll
        for (int it = 0; it < 2; it++) {
            int q = tid + it*128;
            if (q < 160) {
                int c = q >> 3, j4 = q & 7;
                wb[(4*j4+0)*20 + c] = make_float2(wr[it].x, wr[it].x);
                wb[(4*j4+1)*20 + c] = make_float2(wr[it].y, wr[it].y);
                wb[(4*j4+2)*20 + c] = make_float2(wr[it].z, wr[it].z);
                wb[(4*j4+3)*20 + c] = make_float2(wr[it].w, wr[it].w);
            }
        }
    };

    const int tg = tid / 5, cgi = tid % 5;
    const bool active = (tid < 125);

    unsigned long long acc2[8];
#pragma unroll
    for (int i = 0; i < 8; i++) acc2[i] = 0ULL;

    auto compute = [&](int buf) {
        if (!active) return;
        const float4* eb = es4 + buf*1024;
        const float2* wb = ws2 + buf*640;
#pragma unroll
        for (int j = 0; j < 32; j++) {
            int swz = (j >> 2) & 7;
            ulonglong2 e   = *(const ulonglong2*)(eb + j*32 + (tg ^ swz));
            ulonglong2 w01 = *(const ulonglong2*)(wb + j*20 + cgi*4);
            ulonglong2 w23 = *(const ulonglong2*)(wb + j*20 + cgi*4 + 2);
            ffma2(acc2[0], e.x, w01.x);
            ffma2(acc2[1], e.x, w01.y);
            ffma2(acc2[2], e.x, w23.x);
            ffma2(acc2[3], e.x, w23.y);
            ffma2(acc2[4], e.y, w01.x);
            ffma2(acc2[5], e.y, w01.y);
            ffma2(acc2[6], e.y, w23.x);
            ffma2(acc2[7], e.y, w23.y);
        }
    };

    float4 fr0[7], fr1[7], wr0[2], wr1[2];

    prefetch(0, fr0, wr0);
    prefetch(1, fr1, wr1);
    store_stage(fr0, wr0, 0);      // waits only on chunk-0 LDGs
    __syncthreads();

#pragma unroll 2
    for (int h = 0; h < 16; h++) {
        if ((h & 1) == 0) {
            if (h < 14) prefetch(h + 2, fr0, wr0);   // 2 chunks in flight
            compute(0);
            if (h < 15) store_stage(fr1, wr1, 1);    // writes OTHER buffer
        } else {
            if (h < 14) prefetch(h + 2, fr1, wr1);
            compute(1);
            if (h < 15) store_stage(fr0, wr0, 0);
        }
        __syncthreads();                              // single barrier/chunk
    }

    // unpack token-packed accumulators
    if (active) {
        int t0 = tg*4, c0 = cgi*4;
#pragma unroll
        for (int p = 0; p < 2; p++)
#pragma unroll
            for (int c = 0; c < 4; c++) {
                unsigned long long v = acc2[p*4 + c];
                fs[(t0 + 2*p    )*21 + c0 + c] = __uint_as_float((unsigned)v);
                fs[(t0 + 2*p + 1)*21 + c0 + c] = __uint_as_float((unsigned)(v >> 32));
            }
    }
    __syncthreads();

    // BN1 stats per (side, channel); wxy load in parallel (es dead)
    if (tid < 40) {
        int u = tid / 20, c = tid % 20;
        float s = 0.f, s2 = 0.f;
#pragma unroll 10
        for (int l = 0; l < 50; l++) {
            float v = fs[(u*50 + l)*21 + c];
            s += v; s2 += v*v;
        }
        float mu  = s * (1.f/50.f);
        float var = s2 * (1.f/50.f) - mu*mu;
        float sc  = g1[c] * rsqrtf(var + EPSV);
        bn[tid]      = sc;
        bn[40 + tid] = beta1[c] - mu*sc;
    }
    for (int q = tid; q < 4800; q += 128) wxy[q] = g_Wxy[q];
    __syncthreads();

    // BN1 apply + relu + pool1 -> m[u][c][x]
    for (int q = tid; q < 1000; q += 128) {
        int u = q / 500, r = q % 500;
        int c = r / 25, x = r % 25;
        float sc = bn[u*20 + c], sh = bn[40 + u*20 + c];
        float a0 = fs[(u*50 + 2*x    )*21 + c]*sc + sh;
        float a1 = fs[(u*50 + 2*x + 1)*21 + c]*sc + sh;
        m[u*500 + c*25 + x] = fmaxf(fmaxf(a0, a1), 0.f);
    }
    __syncthreads();

    // conv1d: thread = (side u, out-channel o); all 23 x in registers.
    if (tid < 80) {
        int u = tid / 40, o = tid % 40;
        const float* wb = wxy + u*2400 + o*60;
        const float* mu_ = m + u*500;
        float acc[23];
#pragma unroll
        for (int x = 0; x < 23; x++) acc[x] = 0.f;
#pragma unroll
        for (int c = 0; c < 20; c++) {
            float w0 = wb[c*3], w1 = wb[c*3+1], w2 = wb[c*3+2];
            const float* mm = mu_ + c*25;
#pragma unroll
            for (int x = 0; x < 23; x++)
                acc[x] += w0*mm[x] + w1*mm[x+1] + w2*mm[x+2];
        }
        float s = 0.f, s2 = 0.f;
        float* dst = &g_A[(size_t)(u*BATCH + b)*920 + o*23];
#pragma unroll
        for (int x = 0; x < 23; x++) {
            float v = acc[x];
            dst[x] = v; s += v; s2 += v*v;
        }
        g_s1[o*1024 + u*512 + b] = s;
        g_s2[o*1024 + u*512 + b] = s2;
    }
}

// ---------------------------------------------------------------------------
// k3: BN2 global stats
// ---------------------------------------------------------------------------
__global__ void k3(const float* __restrict__ g2, const float* __restrict__ beta2)
{
    const int o = blockIdx.x, tid = threadIdx.x;
    __shared__ double rS[256], rQ[256];
    double aS = 0.0, aQ = 0.0;
    for (int b = tid; b < BATCH; b += 256) {
        double sA = g_s1[o*1024 + b],  sB = g_s1[o*1024 + 512 + b];
        double qA = g_s2[o*1024 + b],  qB = g_s2[o*1024 + 512 + b];
        aS += 23.0*(sA + sB);
        aQ += 23.0*qA + 23.0*qB + 2.0*sA*sB;
    }
    rS[tid] = aS; rQ[tid] = aQ;
    __syncthreads();
    for (int s = 128; s > 0; s >>= 1) {
        if (tid < s) { rS[tid] += rS[tid+s]; rQ[tid] += rQ[tid+s]; }
        __syncthreads();
    }
    if (tid == 0) {
        double N    = (double)BATCH * 529.0;
        double mean = rS[0] / N;
        double var  = rQ[0] / N - mean*mean;
        float  sc   = g2[o] * (float)(1.0 / sqrt(var + (double)EPSV));
        g_bn2[o]      = sc;
        g_bn2[C2 + o] = beta2[o] - (float)mean * sc;
    }
}

// ---------------------------------------------------------------------------
// kF: BN2 apply + pool2 + relu + dot(weff) + sigmoid (division-free mainloop)
// ---------------------------------------------------------------------------
__global__ __launch_bounds__(256)
void kF(float* __restrict__ out)
{
    __shared__ float ua[440], vb[440], sh_s[40], red[8];
    const int b = blockIdx.x, tid = threadIdx.x;

    for (int q = tid; q < 880; q += 256) {
        int half = (q >= 440);
        int r = q - half*440;
        int o = r / 11, xx = r - o*11;
        float sc = g_bn2[o];
        const float* p = &g_A[(size_t)(half*BATCH + b)*920 + o*23];
        (half ? vb : ua)[r] = fmaxf(sc*p[2*xx], sc*p[2*xx+1]);
    }
    if (tid < 40) sh_s[tid] = g_bn2[C2 + tid];
    __syncthreads();

    float part = 0.f;
    if (tid < 242) {
        const int half = (tid >= 121);
        const int r  = tid - half*121;
        const int yy = r / 11, xx = r - yy*11;
#pragma unroll
        for (int oo = 0; oo < 20; oo++) {
            int o = 2*oo + half;
            part += g_weff[o*121 + r] *
                    fmaxf(ua[o*11 + xx] + vb[o*11 + yy] + sh_s[o], 0.f);
        }
    }
#pragma unroll
    for (int off = 16; off > 0; off >>= 1)
        part += __shfl_down_sync(0xffffffffu, part, off);
    if ((tid & 31) == 0) red[tid >> 5] = part;
    __syncthreads();
    if (tid == 0) {
        float s = 0.f;
#pragma unroll
        for (int w = 0; w < 8; w++) s += red[w];
        out[b] = 1.f / (1.f + expf(-(s + g_bias0)));
    }
}

// ---------------------------------------------------------------------------
extern "C" void kernel_launch(void* const* d_in, const int* in_sizes, int n_in,
                              void* d_out, int out_size)
{
    const int*   src     = (const int*)  d_in[0];
    const int*   trg     = (const int*)  d_in[1];
    const float* emb_src = (const float*)d_in[3];
    const float* emb_trg = (const float*)d_in[4];
    const float* W1      = (const float*)d_in[5];
    const float* g1      = (const float*)d_in[7];
    const float* beta1   = (const float*)d_in[8];
    const float* W2      = (const float*)d_in[9];
    const float* g2      = (const float*)d_in[11];
    const float* beta2   = (const float*)d_in[12];
    const float* Wfc1    = (const float*)d_in[13];
    const float* bfc1    = (const float*)d_in[14];
    const float* Wfc2    = (const float*)d_in[15];
    const float* bfc2    = (const float*)d_in[16];

    cudaFuncSetAttribute(k1, cudaFuncAttributeMaxDynamicSharedMemorySize, SMEM_K1);

    k0<<<38, 256>>>(W2, Wfc1, Wfc2, bfc1, bfc2);
    k1<<<BATCH, 128, SMEM_K1>>>(src, trg, emb_src, emb_trg, W1, g1, beta1);
    k3<<<C2, 256>>>(g2, beta2);
    kF<<<BATCH, 256>>>((float*)d_out);
}

// round 8
// speedup vs baseline: 1.2291x; 1.2291x over previous
#include <cuda_runtime.h>
#include <math.h>

#define BATCH 512
#define LEN   50
#define EMB   512
#define C1    20
#define C2    40
#define EPSV  1e-5f

// ---------------- device scratch ----------------
__device__ float g_A   [2*BATCH*C2*23];   // [side][b][o][x]
__device__ float g_s1  [C2*2*BATCH];      // [o][side][b]
__device__ float g_s2  [C2*2*BATCH];
__device__ float g_bn2 [2*C2];            // scale | shift
__device__ float g_weff[4840];            // Wfc2 @ Wfc1
__device__ float g_bias0;
__device__ float g_Wxy [2*C2*C1*3];       // Wx | Wy

__device__ __forceinline__ void ffma2(unsigned long long& d,
                                      unsigned long long a, unsigned long long b) {
    asm("fma.rn.f32x2 %0, %1, %2, %0;" : "+l"(d) : "l"(a), "l"(b));
}
__device__ __forceinline__ unsigned smem_u32(const void* p) {
    return (unsigned)__cvta_generic_to_shared(p);
}
__device__ __forceinline__ void cp16(unsigned dst, const void* src) {
    asm volatile("cp.async.cg.shared.global [%0], [%1], 16;" :: "r"(dst), "l"(src));
}
#define CP_COMMIT()  asm volatile("cp.async.commit_group;")
#define CP_WAIT(n)   asm volatile("cp.async.wait_group %0;" :: "n"(n))

// k1 smem layout (bytes). e-tile row stride 516 floats (conflict mitigation).
#define ESP      516
#define OFF_ES   0                        // float es[50*516]      = 103200
#define OFF_WS   103200                   // float ws[2][32*20]    =   5120
#define OFF_FS   108320                   // float fs[50*21]       =   4200
#define OFF_TOK  112520                   // int   tok[50]         =    200
#define OFF_BN   112720                   // float bn[40]          =    160
#define SMEM_K1  112880
// epilogue overlay inside es (dead after GEMM):
#define OFF_WXY  0                        // float wxy[2400] = 9600
#define OFF_M    9600                     // float m[500]    = 2000

// ---------------------------------------------------------------------------
// k0: weight-only precomputes
// ---------------------------------------------------------------------------
__global__ void k0(const float* __restrict__ W2, const float* __restrict__ Wfc1,
                   const float* __restrict__ Wfc2, const float* __restrict__ bfc1,
                   const float* __restrict__ bfc2)
{
    const int blk = blockIdx.x, tid = threadIdx.x;
    if (blk < 19) {
        int k = blk*256 + tid;
        if (k < 4840) {
            float w = 0.f;
#pragma unroll
            for (int c = 0; c < 20; c++) w += Wfc2[c]*Wfc1[c*4840 + k];
            g_weff[k] = w;
        }
        if (blk == 0 && tid == 0) {
            float z = bfc2[0];
#pragma unroll
            for (int c = 0; c < 20; c++) z += Wfc2[c]*bfc1[c];
            g_bias0 = z;
        }
    } else {
        int q = (blk - 19)*256 + tid;
        if (q < 4800) {
            int sside = q / 2400, r = q % 2400;
            int o = r / 60, rc = r % 60, c = rc / 3, d = rc % 3;
            const float* w = W2 + (o*20 + c)*9;
            g_Wxy[q] = sside ? (w[d*3+0] + w[d*3+1] + w[d*3+2])
                             : (w[0*3+d] + w[1*3+d] + w[2*3+d]);
        }
    }
}

// ---------------------------------------------------------------------------
// k1: block = (sample, side). Whole 50x512 e-tile smem-resident via cp.async
// full-row bursts; token-major GEMM; per-side epilogue fused.
// grid (512, 2), 128 threads, 2 blocks/SM.
// ---------------------------------------------------------------------------
__global__ __launch_bounds__(128, 2)
void k1(const int* __restrict__ src, const int* __restrict__ trg,
        const float* __restrict__ emb_src, const float* __restrict__ emb_trg,
        const float* __restrict__ W1, const float* __restrict__ g1,
        const float* __restrict__ beta1)
{
    extern __shared__ char smraw[];
    float*  esf = (float*)(smraw + OFF_ES);
    float*  fs  = (float*)(smraw + OFF_FS);
    int*    tok = (int*  )(smraw + OFF_TOK);
    float*  bn  = (float*)(smraw + OFF_BN);
    float*  wxy = (float*)(smraw + OFF_WXY);
    float*  m   = (float*)(smraw + OFF_M);

    const int tid  = threadIdx.x;
    const int b    = blockIdx.x;
    const int side = blockIdx.y;
    const float* etab = side ? emb_trg : emb_src;

    if (tid < 50) tok[tid] = (side ? trg : src)[b*LEN + tid];
    __syncthreads();

    // ---- e-load: one FULL 2KB row per iteration (128 lanes = 16 consecutive
    // lines requested simultaneously) -> DRAM row bursts, 50 LDGSTS in flight.
    {
        const unsigned es_u = smem_u32(esf);
#pragma unroll 10
        for (int it = 0; it < 50; it++) {
            cp16(es_u + (unsigned)(it*ESP + tid*4)*4,
                 etab + (size_t)tok[it]*EMB + tid*4);
        }
        CP_COMMIT();                                 // group A: e-tile
    }

    // ws staging: chunk h = 32 j x 20 c of W1 (plain float4, no duplication)
    const unsigned ws_u = smem_u32(smraw + OFF_WS);
    auto stage_ws = [&](int h, int buf) {
#pragma unroll
        for (int rep = 0; rep < 2; rep++) {
            int q = tid + rep*128;
            if (q < 160) {                            // q = j4*20 + c
                int j4 = q / 20, c = q - j4*20;
                cp16(ws_u + (unsigned)(buf*2560 + q*16),
                     W1 + c*EMB + h*32 + j4*4);
            }
        }
    };
    stage_ws(0, 0); CP_COMMIT();                     // group B: ws chunk 0

    // ---- GEMM: thread = (token t, channel-half ch); acc packed over j-parity
    const int t  = tid >> 1;                          // 0..63 (valid < 50)
    const int ch = tid & 1;
    const bool active = (t < 50);

    unsigned long long acc2[10];
#pragma unroll
    for (int i = 0; i < 10; i++) acc2[i] = 0ULL;

    for (int h = 0; h < 16; h++) {
        if (h < 15) { stage_ws(h + 1, (h + 1) & 1); CP_COMMIT(); CP_WAIT(1); }
        else        { CP_WAIT(0); }
        __syncthreads();                              // data for chunk h ready
        if (active) {
            const float4* et  = (const float4*)esf + t*(ESP/4) + h*8;
            const float4* wsb = (const float4*)(smraw + OFF_WS + (h & 1)*2560);
#pragma unroll
            for (int j4 = 0; j4 < 8; j4++) {
                float4 e = et[j4];
                ulonglong2 ev = *reinterpret_cast<ulonglong2*>(&e);
#pragma unroll
                for (int ci = 0; ci < 10; ci++) {
                    float4 w = wsb[j4*20 + ch*10 + ci];
                    ulonglong2 wv = *reinterpret_cast<ulonglong2*>(&w);
                    ffma2(acc2[ci], ev.x, wv.x);
                    ffma2(acc2[ci], ev.y, wv.y);
                }
            }
        }
        __syncthreads();                              // compute(h) done before
    }                                                 // buf (h&1) is restaged

    // unpack: f[t][c] = even-j sum + odd-j sum
    if (active) {
#pragma unroll
        for (int ci = 0; ci < 10; ci++) {
            unsigned long long v = acc2[ci];
            fs[t*21 + ch*10 + ci] =
                __uint_as_float((unsigned)v) + __uint_as_float((unsigned)(v >> 32));
        }
    }
    __syncthreads();

    // BN1 stats (20 channels, this side only); wxy load in parallel (es dead)
    if (tid < 20) {
        float s = 0.f, s2 = 0.f;
#pragma unroll 10
        for (int l = 0; l < 50; l++) {
            float v = fs[l*21 + tid];
            s += v; s2 += v*v;
        }
        float mu  = s * (1.f/50.f);
        float var = s2 * (1.f/50.f) - mu*mu;
        float sc  = g1[tid] * rsqrtf(var + EPSV);
        bn[tid]      = sc;
        bn[20 + tid] = beta1[tid] - mu*sc;
    }
    for (int q = tid; q < 2400; q += 128) wxy[q] = g_Wxy[side*2400 + q];
    __syncthreads();

    // BN1 apply + relu + pool1 -> m[c][x]
    for (int q = tid; q < 500; q += 128) {
        int c = q / 25, x = q - c*25;
        float sc = bn[c], sh = bn[20 + c];
        float a0 = fs[(2*x    )*21 + c]*sc + sh;
        float a1 = fs[(2*x + 1)*21 + c]*sc + sh;
        m[c*25 + x] = fmaxf(fmaxf(a0, a1), 0.f);
    }
    __syncthreads();

    // conv1d: thread = out-channel o; all 23 x in registers; sums fused
    if (tid < 40) {
        const int o = tid;
        const float* wb = wxy + o*60;
        float acc[23];
#pragma unroll
        for (int x = 0; x < 23; x++) acc[x] = 0.f;
#pragma unroll
        for (int c = 0; c < 20; c++) {
            float w0 = wb[c*3], w1 = wb[c*3+1], w2 = wb[c*3+2];
            const float* mm = m + c*25;
#pragma unroll
            for (int x = 0; x < 23; x++)
                acc[x] += w0*mm[x] + w1*mm[x+1] + w2*mm[x+2];
        }
        float s = 0.f, s2 = 0.f;
        float* dst = &g_A[(size_t)(side*BATCH + b)*920 + o*23];
#pragma unroll
        for (int x = 0; x < 23; x++) {
            float v = acc[x];
            dst[x] = v; s += v; s2 += v*v;
        }
        g_s1[o*1024 + side*512 + b] = s;
        g_s2[o*1024 + side*512 + b] = s2;
    }
}

// ---------------------------------------------------------------------------
// k3: BN2 global stats
// ---------------------------------------------------------------------------
__global__ void k3(const float* __restrict__ g2, const float* __restrict__ beta2)
{
    const int o = blockIdx.x, tid = threadIdx.x;
    __shared__ double rS[256], rQ[256];
    double aS = 0.0, aQ = 0.0;
    for (int b = tid; b < BATCH; b += 256) {
        double sA = g_s1[o*1024 + b],  sB = g_s1[o*1024 + 512 + b];
        double qA = g_s2[o*1024 + b],  qB = g_s2[o*1024 + 512 + b];
        aS += 23.0*(sA + sB);
        aQ += 23.0*qA + 23.0*qB + 2.0*sA*sB;
    }
    rS[tid] = aS; rQ[tid] = aQ;
    __syncthreads();
    for (int s = 128; s > 0; s >>= 1) {
        if (tid < s) { rS[tid] += rS[tid+s]; rQ[tid] += rQ[tid+s]; }
        __syncthreads();
    }
    if (tid == 0) {
        double N    = (double)BATCH * 529.0;
        double mean = rS[0] / N;
        double var  = rQ[0] / N - mean*mean;
        float  sc   = g2[o] * (float)(1.0 / sqrt(var + (double)EPSV));
        g_bn2[o]      = sc;
        g_bn2[C2 + o] = beta2[o] - (float)mean * sc;
    }
}

// ---------------------------------------------------------------------------
// kF: BN2 apply + pool2 + relu + dot(weff) + sigmoid
// ---------------------------------------------------------------------------
__global__ __launch_bounds__(256)
void kF(float* __restrict__ out)
{
    __shared__ float ua[440], vb[440], sh_s[40], red[8];
    const int b = blockIdx.x, tid = threadIdx.x;

    for (int q = tid; q < 880; q += 256) {
        int half = (q >= 440);
        int r = q - half*440;
        int o = r / 11, xx = r - o*11;
        float sc = g_bn2[o];
        const float* p = &g_A[(size_t)(half*BATCH + b)*920 + o*23];
        (half ? vb : ua)[r] = fmaxf(sc*p[2*xx], sc*p[2*xx+1]);
    }
    if (tid < 40) sh_s[tid] = g_bn2[C2 + tid];
    __syncthreads();

    float part = 0.f;
    if (tid < 242) {
        const int half = (tid >= 121);
        const int r  = tid - half*121;
        const int yy = r / 11, xx = r - yy*11;
#pragma unroll
        for (int oo = 0; oo < 20; oo++) {
            int o = 2*oo + half;
            part += g_weff[o*121 + r] *
                    fmaxf(ua[o*11 + xx] + vb[o*11 + yy] + sh_s[o], 0.f);
        }
    }
#pragma unroll
    for (int off = 16; off > 0; off >>= 1)
        part += __shfl_down_sync(0xffffffffu, part, off);
    if ((tid & 31) == 0) red[tid >> 5] = part;
    __syncthreads();
    if (tid == 0) {
        float s = 0.f;
#pragma unroll
        for (int w = 0; w < 8; w++) s += red[w];
        out[b] = 1.f / (1.f + expf(-(s + g_bias0)));
    }
}

// ---------------------------------------------------------------------------
extern "C" void kernel_launch(void* const* d_in, const int* in_sizes, int n_in,
                              void* d_out, int out_size)
{
    const int*   src     = (const int*)  d_in[0];
    const int*   trg     = (const int*)  d_in[1];
    const float* emb_src = (const float*)d_in[3];
    const float* emb_trg = (const float*)d_in[4];
    const float* W1      = (const float*)d_in[5];
    const float* g1      = (const float*)d_in[7];
    const float* beta1   = (const float*)d_in[8];
    const float* W2      = (const float*)d_in[9];
    const float* g2      = (const float*)d_in[11];
    const float* beta2   = (const float*)d_in[12];
    const float* Wfc1    = (const float*)d_in[13];
    const float* bfc1    = (const float*)d_in[14];
    const float* Wfc2    = (const float*)d_in[15];
    const float* bfc2    = (const float*)d_in[16];

    cudaFuncSetAttribute(k1, cudaFuncAttributeMaxDynamicSharedMemorySize, SMEM_K1);

    k0<<<38, 256>>>(W2, Wfc1, Wfc2, bfc1, bfc2);
    k1<<<dim3(BATCH, 2), 128, SMEM_K1>>>(src, trg, emb_src, emb_trg, W1, g1, beta1);
    k3<<<C2, 256>>>(g2, beta2);
    kF<<<BATCH, 256>>>((float*)d_out);
}

// round 9
// speedup vs baseline: 1.5192x; 1.2360x over previous
#include <cuda_runtime.h>
#include <math.h>

#define BATCH 512
#define LEN   50
#define EMB   512
#define C1    20
#define C2    40
#define EPSV  1e-5f

// ---------------- device scratch ----------------
__device__ float g_A   [2*BATCH*C2*23];   // [side][b][o][x]
__device__ float g_s1  [C2*2*BATCH];      // [o][side][b]
__device__ float g_s2  [C2*2*BATCH];
__device__ float g_bn2 [2*C2];            // scale | shift
__device__ float g_weff[4840];            // Wfc2 @ Wfc1
__device__ float g_bias0;
__device__ float g_Wxy [2*C2*C1*3];       // Wx | Wy
__device__ float g_fp  [2*2*BATCH*1000];  // split-K partials [G][side][b][t*20+c]

__device__ __forceinline__ void ffma2(unsigned long long& d,
                                      unsigned long long a, unsigned long long b) {
    asm("fma.rn.f32x2 %0, %1, %2, %0;" : "+l"(d) : "l"(a), "l"(b));
}
__device__ __forceinline__ unsigned smem_u32(const void* p) {
    return (unsigned)__cvta_generic_to_shared(p);
}
__device__ __forceinline__ void cp16(unsigned dst, const void* src) {
    asm volatile("cp.async.cg.shared.global [%0], [%1], 16;" :: "r"(dst), "l"(src));
}
#define CP_COMMIT()  asm volatile("cp.async.commit_group;")
#define CP_WAIT(n)   asm volatile("cp.async.wait_group %0;" :: "n"(n))

// kS smem layout (bytes). e row stride 260 floats (260 % 32 == 4 -> the
// 16-token LDS.128 pattern lands exactly 2 conflict-free wavefronts).
#define ESP2      260
#define S_OFF_ES  0                       // float es[50*260]   = 52000
#define S_OFF_WS  52000                   // float4 ws[64*20]   = 20480
#define S_OFF_TOK 72480                   // int tok[50]        =   200
#define SMEM_KS   72704

// ---------------------------------------------------------------------------
// k0: weight-only precomputes
// ---------------------------------------------------------------------------
__global__ void k0(const float* __restrict__ W2, const float* __restrict__ Wfc1,
                   const float* __restrict__ Wfc2, const float* __restrict__ bfc1,
                   const float* __restrict__ bfc2)
{
    const int blk = blockIdx.x, tid = threadIdx.x;
    if (blk < 19) {
        int k = blk*256 + tid;
        if (k < 4840) {
            float w = 0.f;
#pragma unroll
            for (int c = 0; c < 20; c++) w += Wfc2[c]*Wfc1[c*4840 + k];
            g_weff[k] = w;
        }
        if (blk == 0 && tid == 0) {
            float z = bfc2[0];
#pragma unroll
            for (int c = 0; c < 20; c++) z += Wfc2[c]*bfc1[c];
            g_bias0 = z;
        }
    } else {
        int q = (blk - 19)*256 + tid;
        if (q < 4800) {
            int sside = q / 2400, r = q % 2400;
            int o = r / 60, rc = r % 60, c = rc / 3, d = rc % 3;
            const float* w = W2 + (o*20 + c)*9;
            g_Wxy[q] = sside ? (w[d*3+0] + w[d*3+1] + w[d*3+2])
                             : (w[0*3+d] + w[1*3+d] + w[2*3+d]);
        }
    }
}

// ---------------------------------------------------------------------------
// kS: split-K GEMM. block = (b, side, G half of K). 128 thr, 3 blocks/SM.
// All loads committed upfront as 4 ordered sub-groups (64 j each); compute
// sub g after wait_group(3-g) -> compute starts after ~13KB, loads overlap.
// ---------------------------------------------------------------------------
__global__ __launch_bounds__(128, 3)
void kS(const int* __restrict__ src, const int* __restrict__ trg,
        const float* __restrict__ emb_src, const float* __restrict__ emb_trg,
        const float* __restrict__ W1)
{
    extern __shared__ char smraw[];
    float*  esf = (float*)(smraw + S_OFF_ES);
    int*    tok = (int*  )(smraw + S_OFF_TOK);

    const int tid  = threadIdx.x;
    const int b    = blockIdx.x;
    const int side = blockIdx.y;
    const int G    = blockIdx.z;           // K half: j in [G*256, G*256+256)
    const float* etab = side ? emb_trg : emb_src;

    if (tid < 50) tok[tid] = (side ? trg : src)[b*LEN + tid];
    __syncthreads();

    const unsigned es_u = smem_u32(smraw + S_OFF_ES);
    const unsigned ws_u = smem_u32(smraw + S_OFF_WS);

    // commit 4 sub-groups: sub covers 64 j (16 j4) of e AND W1
#pragma unroll
    for (int sub = 0; sub < 4; sub++) {
        // e: 50 rows x 64 floats = 800 cp16 (per-warp 2 rows x 256B bursts)
#pragma unroll
        for (int rep = 0; rep < 7; rep++) {
            int idx = tid + rep*128;
            if (idx < 800) {
                int row = idx >> 4, sl = idx & 15;
                cp16(es_u + (unsigned)((row*ESP2 + sub*64 + sl*4)*4),
                     etab + (size_t)tok[row]*EMB + G*256 + sub*64 + sl*4);
            }
        }
        // W1: 16 j4 x 20 c = 320 cp16 into transposed [j4][c] float4 layout
#pragma unroll
        for (int rep = 0; rep < 3; rep++) {
            int q = tid + rep*128;
            if (q < 320) {
                int j4 = q / 20, c = q - j4*20;
                int j4l = sub*16 + j4;
                cp16(ws_u + (unsigned)((j4l*20 + c)*16),
                     W1 + c*EMB + G*256 + j4l*4);
            }
        }
        CP_COMMIT();
    }

    const int t  = tid >> 1;               // token 0..63 (valid < 50)
    const int ch = tid & 1;                // channel half
    const bool active = (t < 50);

    unsigned long long acc2[10];
#pragma unroll
    for (int i = 0; i < 10; i++) acc2[i] = 0ULL;

    const float4* wsb = (const float4*)(smraw + S_OFF_WS);

#pragma unroll
    for (int sub = 0; sub < 4; sub++) {
        switch (sub) {                     // wait for THIS sub-group only
            case 0: CP_WAIT(3); break;
            case 1: CP_WAIT(2); break;
            case 2: CP_WAIT(1); break;
            default: CP_WAIT(0); break;
        }
        __syncthreads();
        if (active) {
            const float4* et = (const float4*)(esf + t*ESP2 + sub*64);
#pragma unroll
            for (int j4 = 0; j4 < 16; j4++) {
                float4 e = et[j4];
                ulonglong2 ev = *reinterpret_cast<ulonglong2*>(&e);
                const float4* wrow = wsb + (sub*16 + j4)*20 + ch*10;
#pragma unroll
                for (int ci = 0; ci < 10; ci++) {
                    float4 w = wrow[ci];
                    ulonglong2 wv = *reinterpret_cast<ulonglong2*>(&w);
                    ffma2(acc2[ci], ev.x, wv.x);
                    ffma2(acc2[ci], ev.y, wv.y);
                }
            }
        }
    }

    // partial f -> global (coalesced: warp writes 1280 consecutive bytes)
    if (active) {
        float* dst = &g_fp[((size_t)(G*1024 + side*512 + b))*1000 + t*20 + ch*10];
#pragma unroll
        for (int ci = 0; ci < 10; ci++) {
            unsigned long long v = acc2[ci];
            dst[ci] = __uint_as_float((unsigned)v) + __uint_as_float((unsigned)(v >> 32));
        }
    }
}

// ---------------------------------------------------------------------------
// kE: per (b, side) — sum split-K partials, BN1 + relu + pool1 + conv1d + sums
// ---------------------------------------------------------------------------
__global__ __launch_bounds__(128)
void kE(const float* __restrict__ g1, const float* __restrict__ beta1)
{
    __shared__ float fs[50*21];
    __shared__ float wxy[2400];
    __shared__ float m[500];
    __shared__ float bn[40];

    const int tid  = threadIdx.x;
    const int b    = blockIdx.x;
    const int side = blockIdx.y;

    const float* p0 = &g_fp[((size_t)(          side*512 + b))*1000];
    const float* p1 = &g_fp[((size_t)(1024 +    side*512 + b))*1000];
    for (int q = tid; q < 1000; q += 128) {
        int t = q / 20, c = q - t*20;
        fs[t*21 + c] = p0[q] + p1[q];
    }
    for (int q = tid; q < 2400; q += 128) wxy[q] = g_Wxy[side*2400 + q];
    __syncthreads();

    // BN1 stats (this side's 20 channels over 50 positions)
    if (tid < 20) {
        float s = 0.f, s2 = 0.f;
#pragma unroll 10
        for (int l = 0; l < 50; l++) {
            float v = fs[l*21 + tid];
            s += v; s2 += v*v;
        }
        float mu  = s * (1.f/50.f);
        float var = s2 * (1.f/50.f) - mu*mu;
        float sc  = g1[tid] * rsqrtf(var + EPSV);
        bn[tid]      = sc;
        bn[20 + tid] = beta1[tid] - mu*sc;
    }
    __syncthreads();

    // BN1 apply + relu + pool1 -> m[c][x]
    for (int q = tid; q < 500; q += 128) {
        int c = q / 25, x = q - c*25;
        float sc = bn[c], sh = bn[20 + c];
        float a0 = fs[(2*x    )*21 + c]*sc + sh;
        float a1 = fs[(2*x + 1)*21 + c]*sc + sh;
        m[c*25 + x] = fmaxf(fmaxf(a0, a1), 0.f);
    }
    __syncthreads();

    // conv1d: thread = out-channel o; sums fused
    if (tid < 40) {
        const int o = tid;
        const float* wb = wxy + o*60;
        float acc[23];
#pragma unroll
        for (int x = 0; x < 23; x++) acc[x] = 0.f;
#pragma unroll
        for (int c = 0; c < 20; c++) {
            float w0 = wb[c*3], w1 = wb[c*3+1], w2 = wb[c*3+2];
            const float* mm = m + c*25;
#pragma unroll
            for (int x = 0; x < 23; x++)
                acc[x] += w0*mm[x] + w1*mm[x+1] + w2*mm[x+2];
        }
        float s = 0.f, s2 = 0.f;
        float* dst = &g_A[(size_t)(side*BATCH + b)*920 + o*23];
#pragma unroll
        for (int x = 0; x < 23; x++) {
            float v = acc[x];
            dst[x] = v; s += v; s2 += v*v;
        }
        g_s1[o*1024 + side*512 + b] = s;
        g_s2[o*1024 + side*512 + b] = s2;
    }
}

// ---------------------------------------------------------------------------
// k3: BN2 global stats
// ---------------------------------------------------------------------------
__global__ void k3(const float* __restrict__ g2, const float* __restrict__ beta2)
{
    const int o = blockIdx.x, tid = threadIdx.x;
    __shared__ double rS[256], rQ[256];
    double aS = 0.0, aQ = 0.0;
    for (int b = tid; b < BATCH; b += 256) {
        double sA = g_s1[o*1024 + b],  sB = g_s1[o*1024 + 512 + b];
        double qA = g_s2[o*1024 + b],  qB = g_s2[o*1024 + 512 + b];
        aS += 23.0*(sA + sB);
        aQ += 23.0*qA + 23.0*qB + 2.0*sA*sB;
    }
    rS[tid] = aS; rQ[tid] = aQ;
    __syncthreads();
    for (int s = 128; s > 0; s >>= 1) {
        if (tid < s) { rS[tid] += rS[tid+s]; rQ[tid] += rQ[tid+s]; }
        __syncthreads();
    }
    if (tid == 0) {
        double N    = (double)BATCH * 529.0;
        double mean = rS[0] / N;
        double var  = rQ[0] / N - mean*mean;
        float  sc   = g2[o] * (float)(1.0 / sqrt(var + (double)EPSV));
        g_bn2[o]      = sc;
        g_bn2[C2 + o] = beta2[o] - (float)mean * sc;
    }
}

// ---------------------------------------------------------------------------
// kF: BN2 apply + pool2 + relu + dot(weff) + sigmoid
// ---------------------------------------------------------------------------
__global__ __launch_bounds__(256)
void kF(float* __restrict__ out)
{
    __shared__ float ua[440], vb[440], sh_s[40], red[8];
    const int b = blockIdx.x, tid = threadIdx.x;

    for (int q = tid; q < 880; q += 256) {
        int half = (q >= 440);
        int r = q - half*440;
        int o = r / 11, xx = r - o*11;
        float sc = g_bn2[o];
        const float* p = &g_A[(size_t)(half*BATCH + b)*920 + o*23];
        (half ? vb : ua)[r] = fmaxf(sc*p[2*xx], sc*p[2*xx+1]);
    }
    if (tid < 40) sh_s[tid] = g_bn2[C2 + tid];
    __syncthreads();

    float part = 0.f;
    if (tid < 242) {
        const int half = (tid >= 121);
        const int r  = tid - half*121;
        const int yy = r / 11, xx = r - yy*11;
#pragma unroll
        for (int oo = 0; oo < 20; oo++) {
            int o = 2*oo + half;
            part += g_weff[o*121 + r] *
                    fmaxf(ua[o*11 + xx] + vb[o*11 + yy] + sh_s[o], 0.f);
        }
    }
#pragma unroll
    for (int off = 16; off > 0; off >>= 1)
        part += __shfl_down_sync(0xffffffffu, part, off);
    if ((tid & 31) == 0) red[tid >> 5] = part;
    __syncthreads();
    if (tid == 0) {
        float s = 0.f;
#pragma unroll
        for (int w = 0; w < 8; w++) s += red[w];
        out[b] = 1.f / (1.f + expf(-(s + g_bias0)));
    }
}

// ---------------------------------------------------------------------------
extern "C" void kernel_launch(void* const* d_in, const int* in_sizes, int n_in,
                              void* d_out, int out_size)
{
    const int*   src     = (const int*)  d_in[0];
    const int*   trg     = (const int*)  d_in[1];
    const float* emb_src = (const float*)d_in[3];
    const float* emb_trg = (const float*)d_in[4];
    const float* W1      = (const float*)d_in[5];
    const float* g1      = (const float*)d_in[7];
    const float* beta1   = (const float*)d_in[8];
    const float* W2      = (const float*)d_in[9];
    const float* g2      = (const float*)d_in[11];
    const float* beta2   = (const float*)d_in[12];
    const float* Wfc1    = (const float*)d_in[13];
    const float* bfc1    = (const float*)d_in[14];
    const float* Wfc2    = (const float*)d_in[15];
    const float* bfc2    = (const float*)d_in[16];

    cudaFuncSetAttribute(kS, cudaFuncAttributeMaxDynamicSharedMemorySize, SMEM_KS);

    k0<<<38, 256>>>(W2, Wfc1, Wfc2, bfc1, bfc2);
    kS<<<dim3(BATCH, 2, 2), 128, SMEM_KS>>>(src, trg, emb_src, emb_trg, W1);
    kE<<<dim3(BATCH, 2), 128>>>(g1, beta1);
    k3<<<C2, 256>>>(g2, beta2);
    kF<<<BATCH, 256>>>((float*)d_out);
}

// round 10
// speedup vs baseline: 1.5242x; 1.0033x over previous
#include <cuda_runtime.h>
#include <math.h>

#define BATCH 512
#define LEN   50
#define EMB   512
#define C1    20
#define C2    40
#define EPSV  1e-5f
#define NG    4                           // K split factor (128 j per part)

// ---------------- device scratch ----------------
__device__ float g_A   [2*BATCH*C2*23];   // [side][b][o][x]
__device__ float g_s1  [C2*2*BATCH];      // [o][side][b]
__device__ float g_s2  [C2*2*BATCH];
__device__ float g_bn2 [2*C2];            // scale | shift
__device__ float g_weff[4840];            // Wfc2 @ Wfc1
__device__ float g_bias0;
__device__ float g_Wxy [2*C2*C1*3];       // Wx | Wy
__device__ float g_fp  [NG*2*BATCH*1000]; // split-K partials [G][side][b][t*20+c]

__device__ __forceinline__ void ffma2(unsigned long long& d,
                                      unsigned long long a, unsigned long long b) {
    asm("fma.rn.f32x2 %0, %1, %2, %0;" : "+l"(d) : "l"(a), "l"(b));
}
__device__ __forceinline__ unsigned smem_u32(const void* p) {
    return (unsigned)__cvta_generic_to_shared(p);
}
__device__ __forceinline__ void cp16(unsigned dst, const void* src) {
    asm volatile("cp.async.cg.shared.global [%0], [%1], 16;" :: "r"(dst), "l"(src));
}
#define CP_COMMIT()  asm volatile("cp.async.commit_group;")
#define CP_WAIT(n)   asm volatile("cp.async.wait_group %0;" :: "n"(n))

// kS smem layout (bytes). e row stride 132 floats (132 % 32 == 4, same
// conflict behavior as R8's 260 which measured fine).
#define ESP3      132
#define S_OFF_ES  0                       // float es[50*132]   = 26400
#define S_OFF_WS  26400                   // float4 ws[32*20]   = 10240
#define S_OFF_TOK 36640                   // int tok[50]        =   200
#define SMEM_KS   36864

// ---------------------------------------------------------------------------
// k0: weight-only precomputes
// ---------------------------------------------------------------------------
__global__ void k0(const float* __restrict__ W2, const float* __restrict__ Wfc1,
                   const float* __restrict__ Wfc2, const float* __restrict__ bfc1,
                   const float* __restrict__ bfc2)
{
    const int blk = blockIdx.x, tid = threadIdx.x;
    if (blk < 19) {
        int k = blk*256 + tid;
        if (k < 4840) {
            float w = 0.f;
#pragma unroll
            for (int c = 0; c < 20; c++) w += Wfc2[c]*Wfc1[c*4840 + k];
            g_weff[k] = w;
        }
        if (blk == 0 && tid == 0) {
            float z = bfc2[0];
#pragma unroll
            for (int c = 0; c < 20; c++) z += Wfc2[c]*bfc1[c];
            g_bias0 = z;
        }
    } else {
        int q = (blk - 19)*256 + tid;
        if (q < 4800) {
            int sside = q / 2400, r = q % 2400;
            int o = r / 60, rc = r % 60, c = rc / 3, d = rc % 3;
            const float* w = W2 + (o*20 + c)*9;
            g_Wxy[q] = sside ? (w[d*3+0] + w[d*3+1] + w[d*3+2])
                             : (w[0*3+d] + w[1*3+d] + w[2*3+d]);
        }
    }
}

// ---------------------------------------------------------------------------
// kS: split-K GEMM. block = (b, side, G quarter of K). 128 thr, 6 blocks/SM.
// Loads committed upfront as 2 ordered sub-groups (64 j each); compute sub g
// after wait_group(1-g) -> compute starts after ~18KB, loads overlap.
// ---------------------------------------------------------------------------
__global__ __launch_bounds__(128, 6)
void kS(const int* __restrict__ src, const int* __restrict__ trg,
        const float* __restrict__ emb_src, const float* __restrict__ emb_trg,
        const float* __restrict__ W1)
{
    extern __shared__ char smraw[];
    float*  esf = (float*)(smraw + S_OFF_ES);
    int*    tok = (int*  )(smraw + S_OFF_TOK);

    const int tid  = threadIdx.x;
    const int b    = blockIdx.x;
    const int side = blockIdx.y;
    const int G    = blockIdx.z;           // K quarter: j in [G*128, G*128+128)
    const float* etab = side ? emb_trg : emb_src;

    if (tid < 50) tok[tid] = (side ? trg : src)[b*LEN + tid];
    __syncthreads();

    const unsigned es_u = smem_u32(smraw + S_OFF_ES);
    const unsigned ws_u = smem_u32(smraw + S_OFF_WS);

    // commit 2 sub-groups: sub covers 64 j (16 j4) of e AND W1
#pragma unroll
    for (int sub = 0; sub < 2; sub++) {
        // e: 50 rows x 64 floats = 800 cp16 (full 256B bursts per row-half)
#pragma unroll
        for (int rep = 0; rep < 7; rep++) {
            int idx = tid + rep*128;
            if (idx < 800) {
                int row = idx >> 4, sl = idx & 15;
                cp16(es_u + (unsigned)((row*ESP3 + sub*64 + sl*4)*4),
                     etab + (size_t)tok[row]*EMB + G*128 + sub*64 + sl*4);
            }
        }
        // W1: 16 j4 x 20 c = 320 cp16 into transposed [j4][c] float4 layout
#pragma unroll
        for (int rep = 0; rep < 3; rep++) {
            int q = tid + rep*128;
            if (q < 320) {
                int j4 = q / 20, c = q - j4*20;
                int j4l = sub*16 + j4;
                cp16(ws_u + (unsigned)((j4l*20 + c)*16),
                     W1 + c*EMB + G*128 + j4l*4);
            }
        }
        CP_COMMIT();
    }

    const int t  = tid >> 1;               // token 0..63 (valid < 50)
    const int ch = tid & 1;                // channel half
    const bool active = (t < 50);

    unsigned long long acc2[10];
#pragma unroll
    for (int i = 0; i < 10; i++) acc2[i] = 0ULL;

    const float4* wsb = (const float4*)(smraw + S_OFF_WS);

#pragma unroll
    for (int sub = 0; sub < 2; sub++) {
        if (sub == 0) CP_WAIT(1); else CP_WAIT(0);
        __syncthreads();
        if (active) {
            const float4* et = (const float4*)(esf + t*ESP3 + sub*64);
#pragma unroll
            for (int j4 = 0; j4 < 16; j4++) {
                float4 e = et[j4];
                ulonglong2 ev = *reinterpret_cast<ulonglong2*>(&e);
                const float4* wrow = wsb + (sub*16 + j4)*20 + ch*10;
#pragma unroll
                for (int ci = 0; ci < 10; ci++) {
                    float4 w = wrow[ci];
                    ulonglong2 wv = *reinterpret_cast<ulonglong2*>(&w);
                    ffma2(acc2[ci], ev.x, wv.x);
                    ffma2(acc2[ci], ev.y, wv.y);
                }
            }
        }
    }

    // partial f -> global (coalesced)
    if (active) {
        float* dst = &g_fp[((size_t)((G*2 + side)*512 + b))*1000 + t*20 + ch*10];
#pragma unroll
        for (int ci = 0; ci < 10; ci++) {
            unsigned long long v = acc2[ci];
            dst[ci] = __uint_as_float((unsigned)v) + __uint_as_float((unsigned)(v >> 32));
        }
    }
}

// ---------------------------------------------------------------------------
// kE: per (b, side) — sum split-K partials, BN1 + relu + pool1 + conv1d + sums
// ---------------------------------------------------------------------------
__global__ __launch_bounds__(128)
void kE(const float* __restrict__ g1, const float* __restrict__ beta1)
{
    __shared__ float fs[50*21];
    __shared__ float wxy[2400];
    __shared__ float m[500];
    __shared__ float bn[40];

    const int tid  = threadIdx.x;
    const int b    = blockIdx.x;
    const int side = blockIdx.y;

    const float* p0 = &g_fp[((size_t)((0*2 + side)*512 + b))*1000];
    const float* p1 = &g_fp[((size_t)((1*2 + side)*512 + b))*1000];
    const float* p2 = &g_fp[((size_t)((2*2 + side)*512 + b))*1000];
    const float* p3 = &g_fp[((size_t)((3*2 + side)*512 + b))*1000];
    for (int q = tid; q < 1000; q += 128) {
        int t = q / 20, c = q - t*20;
        fs[t*21 + c] = (p0[q] + p1[q]) + (p2[q] + p3[q]);
    }
    for (int q = tid; q < 2400; q += 128) wxy[q] = g_Wxy[side*2400 + q];
    __syncthreads();

    // BN1 stats (this side's 20 channels over 50 positions)
    if (tid < 20) {
        float s = 0.f, s2 = 0.f;
#pragma unroll 10
        for (int l = 0; l < 50; l++) {
            float v = fs[l*21 + tid];
            s += v; s2 += v*v;
        }
        float mu  = s * (1.f/50.f);
        float var = s2 * (1.f/50.f) - mu*mu;
        float sc  = g1[tid] * rsqrtf(var + EPSV);
        bn[tid]      = sc;
        bn[20 + tid] = beta1[tid] - mu*sc;
    }
    __syncthreads();

    // BN1 apply + relu + pool1 -> m[c][x]
    for (int q = tid; q < 500; q += 128) {
        int c = q / 25, x = q - c*25;
        float sc = bn[c], sh = bn[20 + c];
        float a0 = fs[(2*x    )*21 + c]*sc + sh;
        float a1 = fs[(2*x + 1)*21 + c]*sc + sh;
        m[c*25 + x] = fmaxf(fmaxf(a0, a1), 0.f);
    }
    __syncthreads();

    // conv1d: thread = out-channel o; sums fused
    if (tid < 40) {
        const int o = tid;
        const float* wb = wxy + o*60;
        float acc[23];
#pragma unroll
        for (int x = 0; x < 23; x++) acc[x] = 0.f;
#pragma unroll
        for (int c = 0; c < 20; c++) {
            float w0 = wb[c*3], w1 = wb[c*3+1], w2 = wb[c*3+2];
            const float* mm = m + c*25;
#pragma unroll
            for (int x = 0; x < 23; x++)
                acc[x] += w0*mm[x] + w1*mm[x+1] + w2*mm[x+2];
        }
        float s = 0.f, s2 = 0.f;
        float* dst = &g_A[(size_t)(side*BATCH + b)*920 + o*23];
#pragma unroll
        for (int x = 0; x < 23; x++) {
            float v = acc[x];
            dst[x] = v; s += v; s2 += v*v;
        }
        g_s1[o*1024 + side*512 + b] = s;
        g_s2[o*1024 + side*512 + b] = s2;
    }
}

// ---------------------------------------------------------------------------
// k3: BN2 global stats
// ---------------------------------------------------------------------------
__global__ void k3(const float* __restrict__ g2, const float* __restrict__ beta2)
{
    const int o = blockIdx.x, tid = threadIdx.x;
    __shared__ double rS[256], rQ[256];
    double aS = 0.0, aQ = 0.0;
    for (int b = tid; b < BATCH; b += 256) {
        double sA = g_s1[o*1024 + b],  sB = g_s1[o*1024 + 512 + b];
        double qA = g_s2[o*1024 + b],  qB = g_s2[o*1024 + 512 + b];
        aS += 23.0*(sA + sB);
        aQ += 23.0*qA + 23.0*qB + 2.0*sA*sB;
    }
    rS[tid] = aS; rQ[tid] = aQ;
    __syncthreads();
    for (int s = 128; s > 0; s >>= 1) {
        if (tid < s) { rS[tid] += rS[tid+s]; rQ[tid] += rQ[tid+s]; }
        __syncthreads();
    }
    if (tid == 0) {
        double N    = (double)BATCH * 529.0;
        double mean = rS[0] / N;
        double var  = rQ[0] / N - mean*mean;
        float  sc   = g2[o] * (float)(1.0 / sqrt(var + (double)EPSV));
        g_bn2[o]      = sc;
        g_bn2[C2 + o] = beta2[o] - (float)mean * sc;
    }
}

// ---------------------------------------------------------------------------
// kF: BN2 apply + pool2 + relu + dot(weff) + sigmoid
// ---------------------------------------------------------------------------
__global__ __launch_bounds__(256)
void kF(float* __restrict__ out)
{
    __shared__ float ua[440], vb[440], sh_s[40], red[8];
    const int b = blockIdx.x, tid = threadIdx.x;

    for (int q = tid; q < 880; q += 256) {
        int half = (q >= 440);
        int r = q - half*440;
        int o = r / 11, xx = r - o*11;
        float sc = g_bn2[o];
        const float* p = &g_A[(size_t)(half*BATCH + b)*920 + o*23];
        (half ? vb : ua)[r] = fmaxf(sc*p[2*xx], sc*p[2*xx+1]);
    }
    if (tid < 40) sh_s[tid] = g_bn2[C2 + tid];
    __syncthreads();

    float part = 0.f;
    if (tid < 242) {
        const int half = (tid >= 121);
        const int r  = tid - half*121;
        const int yy = r / 11, xx = r - yy*11;
#pragma unroll
        for (int oo = 0; oo < 20; oo++) {
            int o = 2*oo + half;
            part += g_weff[o*121 + r] *
                    fmaxf(ua[o*11 + xx] + vb[o*11 + yy] + sh_s[o], 0.f);
        }
    }
#pragma unroll
    for (int off = 16; off > 0; off >>= 1)
        part += __shfl_down_sync(0xffffffffu, part, off);
    if ((tid & 31) == 0) red[tid >> 5] = part;
    __syncthreads();
    if (tid == 0) {
        float s = 0.f;
#pragma unroll
        for (int w = 0; w < 8; w++) s += red[w];
        out[b] = 1.f / (1.f + expf(-(s + g_bias0)));
    }
}

// ---------------------------------------------------------------------------
extern "C" void kernel_launch(void* const* d_in, const int* in_sizes, int n_in,
                              void* d_out, int out_size)
{
    const int*   src     = (const int*)  d_in[0];
    const int*   trg     = (const int*)  d_in[1];
    const float* emb_src = (const float*)d_in[3];
    const float* emb_trg = (const float*)d_in[4];
    const float* W1      = (const float*)d_in[5];
    const float* g1      = (const float*)d_in[7];
    const float* beta1   = (const float*)d_in[8];
    const float* W2      = (const float*)d_in[9];
    const float* g2      = (const float*)d_in[11];
    const float* beta2   = (const float*)d_in[12];
    const float* Wfc1    = (const float*)d_in[13];
    const float* bfc1    = (const float*)d_in[14];
    const float* Wfc2    = (const float*)d_in[15];
    const float* bfc2    = (const float*)d_in[16];

    cudaFuncSetAttribute(kS, cudaFuncAttributeMaxDynamicSharedMemorySize, SMEM_KS);

    k0<<<38, 256>>>(W2, Wfc1, Wfc2, bfc1, bfc2);
    kS<<<dim3(BATCH, 2, NG), 128, SMEM_KS>>>(src, trg, emb_src, emb_trg, W1);
    kE<<<dim3(BATCH, 2), 128>>>(g1, beta1);
    k3<<<C2, 256>>>(g2, beta2);
    kF<<<BATCH, 256>>>((float*)d_out);
}

// round 11
// speedup vs baseline: 1.7282x; 1.1338x over previous
#include <cuda_runtime.h>
#include <math.h>

#define BATCH 512
#define LEN   50
#define EMB   512
#define C1    20
#define C2    40
#define EPSV  1e-5f
#define NG    4                           // K split factor (128 j per part)

// ---------------- device scratch ----------------
__device__ float g_A   [2*BATCH*C2*23];   // [side][b][o][x]
__device__ float g_s1  [C2*2*BATCH];      // [o][side][b]
__device__ float g_s2  [C2*2*BATCH];
__device__ float g_bn2 [2*C2];            // scale | shift
__device__ float g_weff[4840];            // Wfc2 @ Wfc1
__device__ float g_bias0;
__device__ float g_Wxy [2*C2*C1*3];       // Wx | Wy
__device__ float g_fp  [NG*2*BATCH*1000]; // split-K partials [G][side][b][t*20+c]

__device__ __forceinline__ void ffma2(unsigned long long& d,
                                      unsigned long long a, unsigned long long b) {
    asm("fma.rn.f32x2 %0, %1, %2, %0;" : "+l"(d) : "l"(a), "l"(b));
}
__device__ __forceinline__ unsigned smem_u32(const void* p) {
    return (unsigned)__cvta_generic_to_shared(p);
}
// ONE instruction per 512B row: kills the 8-cyc/op cp.async issue floor
__device__ __forceinline__ void bulk_g2s(unsigned dst, const void* src,
                                         unsigned bytes, unsigned bar) {
    asm volatile(
        "cp.async.bulk.shared::cta.global.mbarrier::complete_tx::bytes "
        "[%0], [%1], %2, [%3];"
        :: "r"(dst), "l"(src), "r"(bytes), "r"(bar) : "memory");
}
#define MBAR_INIT(addr, cnt) \
    asm volatile("mbarrier.init.shared.b64 [%0], %1;" :: "r"(addr), "r"(cnt) : "memory")
#define MBAR_EXPECT_TX(addr, bytes) \
    asm volatile("mbarrier.arrive.expect_tx.shared.b64 _, [%0], %1;" \
                 :: "r"(addr), "r"(bytes) : "memory")
#define MBAR_WAIT(addr, parity) do {                                        \
    asm volatile(                                                           \
        "{\n\t.reg .pred P1;\n\t"                                           \
        "WAIT_LOOP_%=:\n\t"                                                 \
        "mbarrier.try_wait.parity.acquire.cta.shared::cta.b64 P1, [%0], %1, 0x989680;\n\t" \
        "@P1 bra.uni WAIT_DONE_%=;\n\t"                                     \
        "bra.uni WAIT_LOOP_%=;\n\t"                                         \
        "WAIT_DONE_%=:\n\t}"                                                \
        :: "r"(addr), "r"(parity) : "memory");                              \
} while (0)

// kS smem layout (bytes). rows padded to 528B (132 floats): 132%32==4 ->
// e-LDS conflict-free (verified R8/R9); w rows bank-distinct per channel.
#define S_OFF_ES  0                       // 50 rows x 528B = 26400
#define S_OFF_WS  26400                   // 20 rows x 528B = 10560
#define S_OFF_BAR 36960                   // mbarrier (8B)
#define SMEM_KS   36992

// ---------------------------------------------------------------------------
// k0: weight-only precomputes
// ---------------------------------------------------------------------------
__global__ void k0(const float* __restrict__ W2, const float* __restrict__ Wfc1,
                   const float* __restrict__ Wfc2, const float* __restrict__ bfc1,
                   const float* __restrict__ bfc2)
{
    const int blk = blockIdx.x, tid = threadIdx.x;
    if (blk < 19) {
        int k = blk*256 + tid;
        if (k < 4840) {
            float w = 0.f;
#pragma unroll
            for (int c = 0; c < 20; c++) w += Wfc2[c]*Wfc1[c*4840 + k];
            g_weff[k] = w;
        }
        if (blk == 0 && tid == 0) {
            float z = bfc2[0];
#pragma unroll
            for (int c = 0; c < 20; c++) z += Wfc2[c]*bfc1[c];
            g_bias0 = z;
        }
    } else {
        int q = (blk - 19)*256 + tid;
        if (q < 4800) {
            int sside = q / 2400, r = q % 2400;
            int o = r / 60, rc = r % 60, c = rc / 3, d = rc % 3;
            const float* w = W2 + (o*20 + c)*9;
            g_Wxy[q] = sside ? (w[d*3+0] + w[d*3+1] + w[d*3+2])
                             : (w[0*3+d] + w[1*3+d] + w[2*3+d]);
        }
    }
}

// ---------------------------------------------------------------------------
// kS: split-K GEMM, TMA-bulk loads. block = (b, side, G). 128 thr, 6/SM.
// 70 bulk copies/block (1 per 512B row) vs 1120 cp16 -> issue floor gone.
// ---------------------------------------------------------------------------
__global__ __launch_bounds__(128, 6)
void kS(const int* __restrict__ src, const int* __restrict__ trg,
        const float* __restrict__ emb_src, const float* __restrict__ emb_trg,
        const float* __restrict__ W1)
{
    extern __shared__ char smraw[];
    float* esf = (float*)(smraw + S_OFF_ES);

    const int tid  = threadIdx.x;
    const int b    = blockIdx.x;
    const int side = blockIdx.y;
    const int G    = blockIdx.z;           // K quarter: j in [G*128, G*128+128)
    const float* etab = side ? emb_trg : emb_src;

    const unsigned bar  = smem_u32(smraw + S_OFF_BAR);
    const unsigned es_u = smem_u32(smraw + S_OFF_ES);
    const unsigned ws_u = smem_u32(smraw + S_OFF_WS);

    if (tid == 0) MBAR_INIT(bar, 1);
    __syncthreads();
    if (tid == 0) MBAR_EXPECT_TX(bar, 70u*512u);
    __syncthreads();

    if (tid < 50) {                       // each thread: ONE bulk copy of its row
        int tv = (side ? trg : src)[b*LEN + tid];
        bulk_g2s(es_u + (unsigned)tid*528u,
                 etab + (size_t)tv*EMB + G*128, 512u, bar);
    } else if (tid >= 64 && tid < 84) {   // W1 rows (row-major, padded stride)
        int c = tid - 64;
        bulk_g2s(ws_u + (unsigned)c*528u,
                 W1 + (size_t)c*EMB + G*128, 512u, bar);
    }

    MBAR_WAIT(bar, 0);

    const int t  = tid >> 1;               // token 0..63 (valid < 50)
    const int ch = tid & 1;                // channel half
    const bool active = (t < 50);

    unsigned long long acc2[10];
#pragma unroll
    for (int i = 0; i < 10; i++) acc2[i] = 0ULL;

    if (active) {
        const float4* et = (const float4*)esf + t*33;          // 33 float4/row
        const float4* wf = (const float4*)(smraw + S_OFF_WS);  // [c][33]
#pragma unroll
        for (int j4 = 0; j4 < 32; j4++) {
            float4 e = et[j4];
            ulonglong2 ev = *reinterpret_cast<ulonglong2*>(&e);
#pragma unroll
            for (int ci = 0; ci < 10; ci++) {
                float4 w = wf[(ch*10 + ci)*33 + j4];
                ulonglong2 wv = *reinterpret_cast<ulonglong2*>(&w);
                ffma2(acc2[ci], ev.x, wv.x);
                ffma2(acc2[ci], ev.y, wv.y);
            }
        }
    }

    // partial f -> global (coalesced)
    if (active) {
        float* dst = &g_fp[((size_t)((G*2 + side)*512 + b))*1000 + t*20 + ch*10];
#pragma unroll
        for (int ci = 0; ci < 10; ci++) {
            unsigned long long v = acc2[ci];
            dst[ci] = __uint_as_float((unsigned)v) + __uint_as_float((unsigned)(v >> 32));
        }
    }
}

// ---------------------------------------------------------------------------
// kE: per (b, side) — sum split-K partials, BN1 + relu + pool1 + conv1d + sums
// ---------------------------------------------------------------------------
__global__ __launch_bounds__(128)
void kE(const float* __restrict__ g1, const float* __restrict__ beta1)
{
    __shared__ float fs[50*21];
    __shared__ float wxy[2400];
    __shared__ float m[500];
    __shared__ float bn[40];

    const int tid  = threadIdx.x;
    const int b    = blockIdx.x;
    const int side = blockIdx.y;

    const float* p0 = &g_fp[((size_t)((0*2 + side)*512 + b))*1000];
    const float* p1 = &g_fp[((size_t)((1*2 + side)*512 + b))*1000];
    const float* p2 = &g_fp[((size_t)((2*2 + side)*512 + b))*1000];
    const float* p3 = &g_fp[((size_t)((3*2 + side)*512 + b))*1000];
    for (int q = tid; q < 1000; q += 128) {
        int t = q / 20, c = q - t*20;
        fs[t*21 + c] = (p0[q] + p1[q]) + (p2[q] + p3[q]);
    }
    for (int q = tid; q < 2400; q += 128) wxy[q] = g_Wxy[side*2400 + q];
    __syncthreads();

    if (tid < 20) {
        float s = 0.f, s2 = 0.f;
#pragma unroll 10
        for (int l = 0; l < 50; l++) {
            float v = fs[l*21 + tid];
            s += v; s2 += v*v;
        }
        float mu  = s * (1.f/50.f);
        float var = s2 * (1.f/50.f) - mu*mu;
        float sc  = g1[tid] * rsqrtf(var + EPSV);
        bn[tid]      = sc;
        bn[20 + tid] = beta1[tid] - mu*sc;
    }
    __syncthreads();

    for (int q = tid; q < 500; q += 128) {
        int c = q / 25, x = q - c*25;
        float sc = bn[c], sh = bn[20 + c];
        float a0 = fs[(2*x    )*21 + c]*sc + sh;
        float a1 = fs[(2*x + 1)*21 + c]*sc + sh;
        m[c*25 + x] = fmaxf(fmaxf(a0, a1), 0.f);
    }
    __syncthreads();

    if (tid < 40) {
        const int o = tid;
        const float* wb = wxy + o*60;
        float acc[23];
#pragma unroll
        for (int x = 0; x < 23; x++) acc[x] = 0.f;
#pragma unroll
        for (int c = 0; c < 20; c++) {
            float w0 = wb[c*3], w1 = wb[c*3+1], w2 = wb[c*3+2];
            const float* mm = m + c*25;
#pragma unroll
            for (int x = 0; x < 23; x++)
                acc[x] += w0*mm[x] + w1*mm[x+1] + w2*mm[x+2];
        }
        float s = 0.f, s2 = 0.f;
        float* dst = &g_A[(size_t)(side*BATCH + b)*920 + o*23];
#pragma unroll
        for (int x = 0; x < 23; x++) {
            float v = acc[x];
            dst[x] = v; s += v; s2 += v*v;
        }
        g_s1[o*1024 + side*512 + b] = s;
        g_s2[o*1024 + side*512 + b] = s2;
    }
}

// ---------------------------------------------------------------------------
// k3: BN2 global stats
// ---------------------------------------------------------------------------
__global__ void k3(const float* __restrict__ g2, const float* __restrict__ beta2)
{
    const int o = blockIdx.x, tid = threadIdx.x;
    __shared__ double rS[256], rQ[256];
    double aS = 0.0, aQ = 0.0;
    for (int b = tid; b < BATCH; b += 256) {
        double sA = g_s1[o*1024 + b],  sB = g_s1[o*1024 + 512 + b];
        double qA = g_s2[o*1024 + b],  qB = g_s2[o*1024 + 512 + b];
        aS += 23.0*(sA + sB);
        aQ += 23.0*qA + 23.0*qB + 2.0*sA*sB;
    }
    rS[tid] = aS; rQ[tid] = aQ;
    __syncthreads();
    for (int s = 128; s > 0; s >>= 1) {
        if (tid < s) { rS[tid] += rS[tid+s]; rQ[tid] += rQ[tid+s]; }
        __syncthreads();
    }
    if (tid == 0) {
        double N    = (double)BATCH * 529.0;
        double mean = rS[0] / N;
        double var  = rQ[0] / N - mean*mean;
        float  sc   = g2[o] * (float)(1.0 / sqrt(var + (double)EPSV));
        g_bn2[o]      = sc;
        g_bn2[C2 + o] = beta2[o] - (float)mean * sc;
    }
}

// ---------------------------------------------------------------------------
// kF: BN2 apply + pool2 + relu + dot(weff) + sigmoid
// ---------------------------------------------------------------------------
__global__ __launch_bounds__(256)
void kF(float* __restrict__ out)
{
    __shared__ float ua[440], vb[440], sh_s[40], red[8];
    const int b = blockIdx.x, tid = threadIdx.x;

    for (int q = tid; q < 880; q += 256) {
        int half = (q >= 440);
        int r = q - half*440;
        int o = r / 11, xx = r - o*11;
        float sc = g_bn2[o];
        const float* p = &g_A[(size_t)(half*BATCH + b)*920 + o*23];
        (half ? vb : ua)[r] = fmaxf(sc*p[2*xx], sc*p[2*xx+1]);
    }
    if (tid < 40) sh_s[tid] = g_bn2[C2 + tid];
    __syncthreads();

    float part = 0.f;
    if (tid < 242) {
        const int half = (tid >= 121);
        const int r  = tid - half*121;
        const int yy = r / 11, xx = r - yy*11;
#pragma unroll
        for (int oo = 0; oo < 20; oo++) {
            int o = 2*oo + half;
            part += g_weff[o*121 + r] *
                    fmaxf(ua[o*11 + xx] + vb[o*11 + yy] + sh_s[o], 0.f);
        }
    }
#pragma unroll
    for (int off = 16; off > 0; off >>= 1)
        part += __shfl_down_sync(0xffffffffu, part, off);
    if ((tid & 31) == 0) red[tid >> 5] = part;
    __syncthreads();
    if (tid == 0) {
        float s = 0.f;
#pragma unroll
        for (int w = 0; w < 8; w++) s += red[w];
        out[b] = 1.f / (1.f + expf(-(s + g_bias0)));
    }
}

// ---------------------------------------------------------------------------
extern "C" void kernel_launch(void* const* d_in, const int* in_sizes, int n_in,
                              void* d_out, int out_size)
{
    const int*   src     = (const int*)  d_in[0];
    const int*   trg     = (const int*)  d_in[1];
    const float* emb_src = (const float*)d_in[3];
    const float* emb_trg = (const float*)d_in[4];
    const float* W1      = (const float*)d_in[5];
    const float* g1      = (const float*)d_in[7];
    const float* beta1   = (const float*)d_in[8];
    const float* W2      = (const float*)d_in[9];
    const float* g2      = (const float*)d_in[11];
    const float* beta2   = (const float*)d_in[12];
    const float* Wfc1    = (const float*)d_in[13];
    const float* bfc1    = (const float*)d_in[14];
    const float* Wfc2    = (const float*)d_in[15];
    const float* bfc2    = (const float*)d_in[16];

    cudaFuncSetAttribute(kS, cudaFuncAttributeMaxDynamicSharedMemorySize, SMEM_KS);

    k0<<<38, 256>>>(W2, Wfc1, Wfc2, bfc1, bfc2);
    kS<<<dim3(BATCH, 2, NG), 128, SMEM_KS>>>(src, trg, emb_src, emb_trg, W1);
    kE<<<dim3(BATCH, 2), 128>>>(g1, beta1);
    k3<<<C2, 256>>>(g2, beta2);
    kF<<<BATCH, 256>>>((float*)d_out);
}

// round 12
// speedup vs baseline: 1.7480x; 1.0115x over previous
#include <cuda_runtime.h>
#include <math.h>

#define BATCH 512
#define LEN   50
#define EMB   512
#define C1    20
#define C2    40
#define EPSV  1e-5f
#define NG    4                           // K split factor (128 j per part)

// ---------------- device scratch ----------------
__device__ float g_A   [2*BATCH*C2*23];   // [side][b][o][x]
__device__ float g_s1  [C2*2*BATCH];      // [o][side][b]
__device__ float g_s2  [C2*2*BATCH];
__device__ float g_bn2 [2*C2];            // scale | shift
__device__ float g_weff[4840];            // Wfc2 @ Wfc1
__device__ float g_bias0;
__device__ float g_Wxy [2*C2*C1*3];       // Wx | Wy
__device__ float g_fp  [NG*2*BATCH*1000]; // split-K partials [G][side][b][t*20+c]

__device__ __forceinline__ void ffma2(unsigned long long& d,
                                      unsigned long long a, unsigned long long b) {
    asm("fma.rn.f32x2 %0, %1, %2, %0;" : "+l"(d) : "l"(a), "l"(b));
}
__device__ __forceinline__ unsigned smem_u32(const void* p) {
    return (unsigned)__cvta_generic_to_shared(p);
}
__device__ __forceinline__ void bulk_g2s(unsigned dst, const void* src,
                                         unsigned bytes, unsigned bar) {
    asm volatile(
        "cp.async.bulk.shared::cta.global.mbarrier::complete_tx::bytes "
        "[%0], [%1], %2, [%3];"
        :: "r"(dst), "l"(src), "r"(bytes), "r"(bar) : "memory");
}
#define MBAR_INIT(addr, cnt) \
    asm volatile("mbarrier.init.shared.b64 [%0], %1;" :: "r"(addr), "r"(cnt) : "memory")
#define MBAR_EXPECT_TX(addr, bytes) \
    asm volatile("mbarrier.arrive.expect_tx.shared.b64 _, [%0], %1;" \
                 :: "r"(addr), "r"(bytes) : "memory")
#define MBAR_WAIT(addr, parity) do {                                        \
    asm volatile(                                                           \
        "{\n\t.reg .pred P1;\n\t"                                           \
        "WAIT_LOOP_%=:\n\t"                                                 \
        "mbarrier.try_wait.parity.acquire.cta.shared::cta.b64 P1, [%0], %1, 0x989680;\n\t" \
        "@P1 bra.uni WAIT_DONE_%=;\n\t"                                     \
        "bra.uni WAIT_LOOP_%=;\n\t"                                         \
        "WAIT_DONE_%=:\n\t}"                                                \
        :: "r"(addr), "r"(parity) : "memory");                              \
} while (0)

// kS smem: rows padded to 528B (132 floats, verified conflict behavior)
#define S_OFF_ES  0                       // 100 rows x 528B = 52800
#define S_OFF_WS  52800                   //  20 rows x 528B = 10560
#define S_OFF_BAR 63360                   // mbarrier (8B)
#define SMEM_KS   63392

// ---------------------------------------------------------------------------
// k0: weight-only precomputes
// ---------------------------------------------------------------------------
__global__ void k0(const float* __restrict__ W2, const float* __restrict__ Wfc1,
                   const float* __restrict__ Wfc2, const float* __restrict__ bfc1,
                   const float* __restrict__ bfc2)
{
    const int blk = blockIdx.x, tid = threadIdx.x;
    if (blk < 19) {
        int k = blk*256 + tid;
        if (k < 4840) {
            float w = 0.f;
#pragma unroll
            for (int c = 0; c < 20; c++) w += Wfc2[c]*Wfc1[c*4840 + k];
            g_weff[k] = w;
        }
        if (blk == 0 && tid == 0) {
            float z = bfc2[0];
#pragma unroll
            for (int c = 0; c < 20; c++) z += Wfc2[c]*bfc1[c];
            g_bias0 = z;
        }
    } else {
        int q = (blk - 19)*256 + tid;
        if (q < 4800) {
            int sside = q / 2400, r = q % 2400;
            int o = r / 60, rc = r % 60, c = rc / 3, d = rc % 3;
            const float* w = W2 + (o*20 + c)*9;
            g_Wxy[q] = sside ? (w[d*3+0] + w[d*3+1] + w[d*3+2])
                             : (w[0*3+d] + w[1*3+d] + w[2*3+d]);
        }
    }
}

// ---------------------------------------------------------------------------
// kS: split-K GEMM, TMA-bulk loads, 2-token x 10-channel thread tile.
// block = (b, G) covering BOTH sides (100 tokens). 128 thr, 3 blocks/SM.
// ---------------------------------------------------------------------------
__global__ __launch_bounds__(128, 3)
void kS(const int* __restrict__ src, const int* __restrict__ trg,
        const float* __restrict__ emb_src, const float* __restrict__ emb_trg,
        const float* __restrict__ W1)
{
    extern __shared__ char smraw[];
    float* esf = (float*)(smraw + S_OFF_ES);

    const int tid = threadIdx.x;
    const int b   = blockIdx.x;
    const int G   = blockIdx.y;            // K quarter: j in [G*128, G*128+128)

    const unsigned bar  = smem_u32(smraw + S_OFF_BAR);
    const unsigned es_u = smem_u32(smraw + S_OFF_ES);
    const unsigned ws_u = smem_u32(smraw + S_OFF_WS);

    if (tid == 0) MBAR_INIT(bar, 1);
    __syncthreads();
    if (tid == 0) MBAR_EXPECT_TX(bar, 120u*512u);
    __syncthreads();

    if (tid < 100) {                       // one bulk copy per token row
        int tv = (tid < 50) ? src[b*LEN + tid] : trg[b*LEN + (tid - 50)];
        const float* etab = (tid < 50) ? emb_src : emb_trg;
        bulk_g2s(es_u + (unsigned)tid*528u,
                 etab + (size_t)tv*EMB + G*128, 512u, bar);
    } else if (tid < 120) {                // W1 rows (row-major, padded stride)
        int c = tid - 100;
        bulk_g2s(ws_u + (unsigned)c*528u,
                 W1 + (size_t)c*EMB + G*128, 512u, bar);
    }

    MBAR_WAIT(bar, 0);

    // thread = (token-pair tpg, channel-half ch); rows r1 = tpg+25*side, r2 = r1+25
    const int ch  = tid & 1;
    const int tpg = tid >> 1;              // 0..63 (valid < 50)
    const bool active = (tpg < 50);
    const int side = (tpg >= 25);
    const int tp   = tpg - side*25;        // seq position of first token
    const int r1   = tpg + side*25;        // smem row (side*50 + tp)
    const int r2   = r1 + 25;

    unsigned long long acc2[20];           // [pair 0/1][ci]
#pragma unroll
    for (int i = 0; i < 20; i++) acc2[i] = 0ULL;

    if (active) {
        const float4* e1 = (const float4*)esf + r1*33;
        const float4* e2 = (const float4*)esf + r2*33;
        const float4* wf = (const float4*)(smraw + S_OFF_WS);  // [c][33]
#pragma unroll
        for (int j4 = 0; j4 < 32; j4++) {
            float4 ea = e1[j4], eb = e2[j4];
            ulonglong2 eva = *reinterpret_cast<ulonglong2*>(&ea);
            ulonglong2 evb = *reinterpret_cast<ulonglong2*>(&eb);
#pragma unroll
            for (int ci = 0; ci < 10; ci++) {
                float4 w = wf[(ch*10 + ci)*33 + j4];
                ulonglong2 wv = *reinterpret_cast<ulonglong2*>(&w);
                ffma2(acc2[ci],      eva.x, wv.x);
                ffma2(acc2[ci],      eva.y, wv.y);
                ffma2(acc2[10 + ci], evb.x, wv.x);
                ffma2(acc2[10 + ci], evb.y, wv.y);
            }
        }
    }

    // partial f -> global (both tokens of the pair)
    if (active) {
        float* base = &g_fp[((size_t)((G*2 + side)*512 + b))*1000];
        float* d1 = base + tp*20       + ch*10;
        float* d2 = base + (tp + 25)*20 + ch*10;
#pragma unroll
        for (int ci = 0; ci < 10; ci++) {
            unsigned long long v = acc2[ci];
            d1[ci] = __uint_as_float((unsigned)v) + __uint_as_float((unsigned)(v >> 32));
            unsigned long long u = acc2[10 + ci];
            d2[ci] = __uint_as_float((unsigned)u) + __uint_as_float((unsigned)(u >> 32));
        }
    }
}

// ---------------------------------------------------------------------------
// kE: per (b, side) — sum split-K partials, BN1 + relu + pool1 + conv1d + sums
// ---------------------------------------------------------------------------
__global__ __launch_bounds__(128)
void kE(const float* __restrict__ g1, const float* __restrict__ beta1)
{
    __shared__ float fs[50*21];
    __shared__ float wxy[2400];
    __shared__ float m[500];
    __shared__ float bn[40];

    const int tid  = threadIdx.x;
    const int b    = blockIdx.x;
    const int side = blockIdx.y;

    const float* p0 = &g_fp[((size_t)((0*2 + side)*512 + b))*1000];
    const float* p1 = &g_fp[((size_t)((1*2 + side)*512 + b))*1000];
    const float* p2 = &g_fp[((size_t)((2*2 + side)*512 + b))*1000];
    const float* p3 = &g_fp[((size_t)((3*2 + side)*512 + b))*1000];
    for (int q = tid; q < 1000; q += 128) {
        int t = q / 20, c = q - t*20;
        fs[t*21 + c] = (p0[q] + p1[q]) + (p2[q] + p3[q]);
    }
    for (int q = tid; q < 2400; q += 128) wxy[q] = g_Wxy[side*2400 + q];
    __syncthreads();

    if (tid < 20) {
        float s = 0.f, s2 = 0.f;
#pragma unroll 10
        for (int l = 0; l < 50; l++) {
            float v = fs[l*21 + tid];
            s += v; s2 += v*v;
        }
        float mu  = s * (1.f/50.f);
        float var = s2 * (1.f/50.f) - mu*mu;
        float sc  = g1[tid] * rsqrtf(var + EPSV);
        bn[tid]      = sc;
        bn[20 + tid] = beta1[tid] - mu*sc;
    }
    __syncthreads();

    for (int q = tid; q < 500; q += 128) {
        int c = q / 25, x = q - c*25;
        float sc = bn[c], sh = bn[20 + c];
        float a0 = fs[(2*x    )*21 + c]*sc + sh;
        float a1 = fs[(2*x + 1)*21 + c]*sc + sh;
        m[c*25 + x] = fmaxf(fmaxf(a0, a1), 0.f);
    }
    __syncthreads();

    if (tid < 40) {
        const int o = tid;
        const float* wb = wxy + o*60;
        float acc[23];
#pragma unroll
        for (int x = 0; x < 23; x++) acc[x] = 0.f;
#pragma unroll
        for (int c = 0; c < 20; c++) {
            float w0 = wb[c*3], w1 = wb[c*3+1], w2 = wb[c*3+2];
            const float* mm = m + c*25;
#pragma unroll
            for (int x = 0; x < 23; x++)
                acc[x] += w0*mm[x] + w1*mm[x+1] + w2*mm[x+2];
        }
        float s = 0.f, s2 = 0.f;
        float* dst = &g_A[(size_t)(side*BATCH + b)*920 + o*23];
#pragma unroll
        for (int x = 0; x < 23; x++) {
            float v = acc[x];
            dst[x] = v; s += v; s2 += v*v;
        }
        g_s1[o*1024 + side*512 + b] = s;
        g_s2[o*1024 + side*512 + b] = s2;
    }
}

// ---------------------------------------------------------------------------
// k3: BN2 global stats. 512 threads, 1 thread = 1 sample, shfl reduction.
// ---------------------------------------------------------------------------
__global__ __launch_bounds__(512)
void k3(const float* __restrict__ g2, const float* __restrict__ beta2)
{
    const int o = blockIdx.x, tid = threadIdx.x;
    __shared__ double wS[16], wQ[16];

    double sA = g_s1[o*1024 + tid],       sB = g_s1[o*1024 + 512 + tid];
    double qA = g_s2[o*1024 + tid],       qB = g_s2[o*1024 + 512 + tid];
    double aS = 23.0*(sA + sB);
    double aQ = 23.0*qA + 23.0*qB + 2.0*sA*sB;

#pragma unroll
    for (int off = 16; off > 0; off >>= 1) {
        aS += __shfl_down_sync(0xffffffffu, aS, off);
        aQ += __shfl_down_sync(0xffffffffu, aQ, off);
    }
    if ((tid & 31) == 0) { wS[tid >> 5] = aS; wQ[tid >> 5] = aQ; }
    __syncthreads();
    if (tid < 32) {
        double s = (tid < 16) ? wS[tid] : 0.0;
        double q = (tid < 16) ? wQ[tid] : 0.0;
#pragma unroll
        for (int off = 8; off > 0; off >>= 1) {
            s += __shfl_down_sync(0xffffffffu, s, off);
            q += __shfl_down_sync(0xffffffffu, q, off);
        }
        if (tid == 0) {
            double N    = (double)BATCH * 529.0;
            double mean = s / N;
            double var  = q / N - mean*mean;
            float  sc   = g2[o] * (float)(1.0 / sqrt(var + (double)EPSV));
            g_bn2[o]      = sc;
            g_bn2[C2 + o] = beta2[o] - (float)mean * sc;
        }
    }
}

// ---------------------------------------------------------------------------
// kF: BN2 apply + pool2 + relu + dot(weff) + sigmoid
// ---------------------------------------------------------------------------
__global__ __launch_bounds__(256)
void kF(float* __restrict__ out)
{
    __shared__ float ua[440], vb[440], sh_s[40], red[8];
    const int b = blockIdx.x, tid = threadIdx.x;

    for (int q = tid; q < 880; q += 256) {
        int half = (q >= 440);
        int r = q - half*440;
        int o = r / 11, xx = r - o*11;
        float sc = g_bn2[o];
        const float* p = &g_A[(size_t)(half*BATCH + b)*920 + o*23];
        (half ? vb : ua)[r] = fmaxf(sc*p[2*xx], sc*p[2*xx+1]);
    }
    if (tid < 40) sh_s[tid] = g_bn2[C2 + tid];
    __syncthreads();

    float part = 0.f;
    if (tid < 242) {
        const int half = (tid >= 121);
        const int r  = tid - half*121;
        const int yy = r / 11, xx = r - yy*11;
#pragma unroll
        for (int oo = 0; oo < 20; oo++) {
            int o = 2*oo + half;
            part += g_weff[o*121 + r] *
                    fmaxf(ua[o*11 + xx] + vb[o*11 + yy] + sh_s[o], 0.f);
        }
    }
#pragma unroll
    for (int off = 16; off > 0; off >>= 1)
        part += __shfl_down_sync(0xffffffffu, part, off);
    if ((tid & 31) == 0) red[tid >> 5] = part;
    __syncthreads();
    if (tid == 0) {
        float s = 0.f;
#pragma unroll
        for (int w = 0; w < 8; w++) s += red[w];
        out[b] = 1.f / (1.f + expf(-(s + g_bias0)));
    }
}

// ---------------------------------------------------------------------------
extern "C" void kernel_launch(void* const* d_in, const int* in_sizes, int n_in,
                              void* d_out, int out_size)
{
    const int*   src     = (const int*)  d_in[0];
    const int*   trg     = (const int*)  d_in[1];
    const float* emb_src = (const float*)d_in[3];
    const float* emb_trg = (const float*)d_in[4];
    const float* W1      = (const float*)d_in[5];
    const float* g1      = (const float*)d_in[7];
    const float* beta1   = (const float*)d_in[8];
    const float* W2      = (const float*)d_in[9];
    const float* g2      = (const float*)d_in[11];
    const float* beta2   = (const float*)d_in[12];
    const float* Wfc1    = (const float*)d_in[13];
    const float* bfc1    = (const float*)d_in[14];
    const float* Wfc2    = (const float*)d_in[15];
    const float* bfc2    = (const float*)d_in[16];

    cudaFuncSetAttribute(kS, cudaFuncAttributeMaxDynamicSharedMemorySize, SMEM_KS);

    k0<<<38, 256>>>(W2, Wfc1, Wfc2, bfc1, bfc2);
    kS<<<dim3(BATCH, NG), 128, SMEM_KS>>>(src, trg, emb_src, emb_trg, W1);
    kE<<<dim3(BATCH, 2), 128>>>(g1, beta1);
    k3<<<C2, 512>>>(g2, beta2);
    kF<<<BATCH, 256>>>((float*)d_out);
}